// round 6
// baseline (speedup 1.0000x reference)
#include <cuda_runtime.h>
#include <cuda_bf16.h>
#include <math.h>
#include <stdint.h>

typedef unsigned long long ull;

#define BB   8
#define FHH  8
#define NN   2048
#define TINN 5
#define HH1  32
#define HH2  64
#define KXX  40
#define NEGV -9e15f
#define TI   128
#define ASTR 72          // A/B smem row stride in bf16 (144B -> conflict-free frags)

// ---------------- scratch ----------------------------------------------------
__device__ float g_h1[BB*NN*HH1];
__device__ float g_wx[BB*NN*4*HH2];
__device__ float g_hs[BB*NN*HH2];
__device__ float g_Wh[BB*NN*HH2];
__device__ float g_s [BB*NN];
__device__ float g_d [BB*NN];
__device__ float g_dmax[BB];
__device__ __align__(16) __nv_bfloat16 g_WhT_hi[BB*HH2*NN];   // [b][c][n]
__device__ __align__(16) __nv_bfloat16 g_WhT_lo[BB*HH2*NN];

// ---------------- f32x2 helpers ----------------------------------------------
__device__ __forceinline__ ull pack2(float lo, float hi) {
    ull r; asm("mov.b64 %0, {%1, %2};" : "=l"(r) : "f"(lo), "f"(hi)); return r;
}
__device__ __forceinline__ void unpack2(ull v, float& lo, float& hi) {
    asm("mov.b64 {%0, %1}, %2;" : "=f"(lo), "=f"(hi) : "l"(v));
}
__device__ __forceinline__ ull ffma2(ull a, ull b, ull c) {
    ull r; asm("fma.rn.f32x2 %0, %1, %2, %3;" : "=l"(r) : "l"(a), "l"(b), "l"(c)); return r;
}
__device__ __forceinline__ float fsig(float x) { return __fdividef(1.f, 1.f + __expf(-x)); }
__device__ __forceinline__ float ftanh(float x) {
    return fmaf(__fdividef(2.f, 1.f + __expf(-2.f*x)), 1.f, -1.f);
}

// ---------------- HMMA m16n8k16 bf16 -> f32 (baseline PTX, assembles on sm_103)
__device__ __forceinline__ void mma16816(float* d, const uint32_t* a,
                                         uint32_t b0, uint32_t b1) {
    asm volatile(
        "mma.sync.aligned.m16n8k16.row.col.f32.bf16.bf16.f32 "
        "{%0,%1,%2,%3}, {%4,%5,%6,%7}, {%8,%9}, {%0,%1,%2,%3};"
        : "+f"(d[0]), "+f"(d[1]), "+f"(d[2]), "+f"(d[3])
        : "r"(a[0]), "r"(a[1]), "r"(a[2]), "r"(a[3]), "r"(b0), "r"(b1));
}

// ============================================================================
// Kernel 1: h1 = elu(x @ W1^T + b1)
// ============================================================================
__global__ void k_h1(const float* __restrict__ hist,
                     const float* __restrict__ W1,
                     const float* __restrict__ b1) {
    __shared__ float w1s[KXX*HH1];
    for (int i = threadIdx.x; i < HH1*KXX; i += 256) {
        int k = i / KXX, idx = i % KXX;
        w1s[idx*HH1 + k] = W1[i];
    }
    __syncthreads();
    int row = blockIdx.x * 8 + (threadIdx.x >> 5);
    int k   = threadIdx.x & 31;
    int t = row / NN, n = row % NN;
    float acc = b1[k];
    #pragma unroll
    for (int tt = 0; tt < TINN; tt++)
        #pragma unroll
        for (int f = 0; f < FHH; f++) {
            float x = hist[((t*FHH + f)*NN + n)*TINN + tt];
            acc = fmaf(x, w1s[(tt*FHH + f)*HH1 + k], acc);
        }
    acc = acc > 0.f ? acc : expm1f(acc);
    g_h1[row*HH1 + k] = acc;
}

// ============================================================================
// Kernel 1b: wx = h1 @ W_ih^T + (b_ih+b_hh), interleaved [u*4+gt]
// ============================================================================
__global__ void k_wx(const float* __restrict__ W_ih,
                     const float* __restrict__ b_ih, const float* __restrict__ b_hh) {
    __shared__ float wih[HH1*256];
    __shared__ float bsI[256];
    __shared__ float h1s[HH1*9];
    int tid = threadIdx.x;
    int row0 = blockIdx.x * 8;
    for (int i = tid; i < HH1*256; i += 256) {
        int j = i >> 8, op = i & 255, u = op >> 2, gt = op & 3;
        wih[i] = W_ih[(gt*64 + u)*HH1 + j];
    }
    { int u = tid >> 2, gt = tid & 3; bsI[tid] = b_ih[gt*64+u] + b_hh[gt*64+u]; }
    { int r = tid & 7, j = tid >> 3; h1s[j*9 + r] = g_h1[(row0 + r)*HH1 + j]; }
    __syncthreads();

    int u  = tid & 63;
    int r0 = (tid >> 6) * 2;
    ull acc[2][2];
    ull b0 = *(const ull*)&bsI[u*4], b1v = *(const ull*)&bsI[u*4+2];
    acc[0][0]=b0; acc[0][1]=b1v; acc[1][0]=b0; acc[1][1]=b1v;
    #pragma unroll 8
    for (int j = 0; j < HH1; j++) {
        ulonglong2 wv = *(const ulonglong2*)&wih[j*256 + u*4];
        float ha = h1s[j*9 + r0], hb = h1s[j*9 + r0 + 1];
        ull ha2 = pack2(ha, ha), hb2 = pack2(hb, hb);
        acc[0][0] = ffma2(wv.x, ha2, acc[0][0]);
        acc[0][1] = ffma2(wv.y, ha2, acc[0][1]);
        acc[1][0] = ffma2(wv.x, hb2, acc[1][0]);
        acc[1][1] = ffma2(wv.y, hb2, acc[1][1]);
    }
    #pragma unroll
    for (int nd = 0; nd < 2; nd++) {
        float v0,v1,v2,v3;
        unpack2(acc[nd][0], v0, v1);
        unpack2(acc[nd][1], v2, v3);
        *(float4*)&g_wx[(size_t)(row0 + r0 + nd)*256 + u*4] = make_float4(v0,v1,v2,v3);
    }
}

// ============================================================================
// Kernel 2: recurrent LSTM (W_hh part only)
// ============================================================================
__global__ void __launch_bounds__(256) k_lstm2(const float* __restrict__ W_hh) {
    extern __shared__ float sm[];
    float* whh = sm;
    float* hsh = whh + 64*256;

    int tid = threadIdx.x;
    for (int i = tid; i < 64*256; i += 256) {
        int j = i >> 8, op = i & 255, u = op >> 2, gt = op & 3;
        whh[i] = W_hh[(gt*64 + u)*HH2 + j];
    }
    for (int i = tid; i < 64*21; i += 256) hsh[i] = 0.f;

    int u  = tid & 63;
    int nq = tid >> 6;
    int node0 = blockIdx.x * 16 + nq*4;

    float c[4] = {0.f,0.f,0.f,0.f};
    float4 wx4[4];
    #pragma unroll
    for (int n = 0; n < 4; n++)
        wx4[n] = *(const float4*)&g_wx[(size_t)(node0 + n)*256 + u*4];

    for (int t = 0; t < BB; t++) {
        __syncthreads();
        ull acc[4][2];
        #pragma unroll
        for (int n = 0; n < 4; n++) {
            acc[n][0] = pack2(wx4[n].x, wx4[n].y);
            acc[n][1] = pack2(wx4[n].z, wx4[n].w);
        }
        if (t < BB-1) {
            #pragma unroll
            for (int n = 0; n < 4; n++)
                wx4[n] = *(const float4*)&g_wx[(size_t)((t+1)*NN + node0 + n)*256 + u*4];
        }
        #pragma unroll 4
        for (int j = 0; j < HH2; j++) {
            ulonglong2 wv = *(const ulonglong2*)&whh[j*256 + u*4];
            #pragma unroll
            for (int n = 0; n < 4; n++) {
                float hv = hsh[j*21 + nq*4 + n];
                ull hv2 = pack2(hv, hv);
                acc[n][0] = ffma2(wv.x, hv2, acc[n][0]);
                acc[n][1] = ffma2(wv.y, hv2, acc[n][1]);
            }
        }
        __syncthreads();
        #pragma unroll
        for (int n = 0; n < 4; n++) {
            float gi,gf,gg,go;
            unpack2(acc[n][0], gi, gf);
            unpack2(acc[n][1], gg, go);
            c[n] = fsig(gf)*c[n] + fsig(gi)*ftanh(gg);
            float h = fsig(go)*ftanh(c[n]);
            hsh[u*21 + nq*4 + n] = h;
            g_hs[(size_t)(t*NN + node0 + n)*HH2 + u] = h;
        }
    }
}

// ============================================================================
// Kernel 3: Wh = hs @ Wg ; s = Wh.a_src ; d = Wh.a_dst
// ============================================================================
__global__ void k_wh(const float* __restrict__ Wg,
                     const float* __restrict__ a_src,
                     const float* __restrict__ a_dst) {
    __shared__ float wgs[64*64];
    __shared__ float hss[64*17];
    __shared__ float ps[16*17];
    __shared__ float pd[16*17];
    int tid = threadIdx.x;
    int row0 = blockIdx.x * 16;
    for (int i = tid; i < 4096; i += 256) wgs[i] = Wg[i];
    for (int i = tid; i < 1024; i += 256) {
        int mm = i >> 6, u = i & 63;
        hss[u*17 + mm] = g_hs[(row0 + mm)*HH2 + u];
    }
    __syncthreads();
    int m  = tid >> 4;
    int cq = tid & 15;
    int c0 = cq * 4;
    ull acc0 = 0ull, acc1 = 0ull;
    #pragma unroll 8
    for (int u = 0; u < 64; u++) {
        float hv = hss[u*17 + m];
        ull hv2 = pack2(hv, hv);
        acc0 = ffma2(*(const ull*)&wgs[u*64 + c0],     hv2, acc0);
        acc1 = ffma2(*(const ull*)&wgs[u*64 + c0 + 2], hv2, acc1);
    }
    float wh[4];
    unpack2(acc0, wh[0], wh[1]);
    unpack2(acc1, wh[2], wh[3]);
    *(float4*)&g_Wh[(row0 + m)*HH2 + c0] = make_float4(wh[0], wh[1], wh[2], wh[3]);
    float psum = 0.f, dsum = 0.f;
    #pragma unroll
    for (int q = 0; q < 4; q++) {
        psum = fmaf(wh[q], a_src[c0 + q], psum);
        dsum = fmaf(wh[q], a_dst[c0 + q], dsum);
    }
    ps[m*17 + cq] = psum;
    pd[m*17 + cq] = dsum;
    __syncthreads();
    if (tid < 16) {
        float s = 0.f, d = 0.f;
        #pragma unroll
        for (int q = 0; q < 16; q++) { s += ps[tid*17 + q]; d += pd[tid*17 + q]; }
        g_s[row0 + tid] = s;
        g_d[row0 + tid] = d;
    }
}

// ============================================================================
// Kernel 3b: transpose Wh -> bf16 hi/lo [b][c][n]
// ============================================================================
__global__ void k_trans() {
    __shared__ float ts[64*65];
    int b  = blockIdx.y;
    int n0 = blockIdx.x * 64;
    int tid = threadIdx.x;
    for (int i = tid; i < 4096; i += 256) {
        int r = i >> 6, c = i & 63;
        ts[r*65 + c] = g_Wh[(size_t)((b << 11) + n0 + r)*64 + c];
    }
    __syncthreads();
    for (int i = tid; i < 2048; i += 256) {
        int c = i >> 5, np = i & 31;
        int n = np * 2;
        float v0 = ts[n*65 + c], v1 = ts[(n+1)*65 + c];
        __nv_bfloat16 h0 = __float2bfloat16(v0);
        __nv_bfloat16 h1 = __float2bfloat16(v1);
        __nv_bfloat16 l0 = __float2bfloat16(v0 - __bfloat162float(h0));
        __nv_bfloat16 l1 = __float2bfloat16(v1 - __bfloat162float(h1));
        size_t o = (size_t)(b*64 + c)*NN + n0 + n;
        __nv_bfloat162 hh; hh.x = h0; hh.y = h1;
        __nv_bfloat162 ll; ll.x = l0; ll.y = l1;
        *(__nv_bfloat162*)&g_WhT_hi[o] = hh;
        *(__nv_bfloat162*)&g_WhT_lo[o] = ll;
    }
}

// ============================================================================
// Kernel 3c: per-batch max of d
// ============================================================================
__global__ void k_dmax() {
    __shared__ float red[8];
    int b = blockIdx.x, tid = threadIdx.x;
    float m = -1e30f;
    for (int i = tid; i < NN; i += 256) m = fmaxf(m, g_d[b*NN + i]);
    #pragma unroll
    for (int o = 16; o > 0; o >>= 1)
        m = fmaxf(m, __shfl_xor_sync(0xffffffffu, m, o));
    if ((tid & 31) == 0) red[tid >> 5] = m;
    __syncthreads();
    if (tid == 0) {
        float mm = red[0];
        #pragma unroll
        for (int q = 1; q < 8; q++) mm = fmaxf(mm, red[q]);
        g_dmax[b] = mm;
    }
}

// ============================================================================
// Kernel 4: GAT via HMMA (mma.sync m16n8k16 bf16, hi/lo split => ~fp32 exact).
// grid (16, 8), 256 thr = 8 warps; warp w owns rows w*16..w*16+15.
// Fixed exp shift M_i = lrelu(s_i + dmax_b) >= e_ij  => no rescaling; D in regs.
// ============================================================================
__global__ void k_gat(const int* __restrict__ adj, float* __restrict__ out) {
    extern __shared__ __nv_bfloat16 dsm[];
    __nv_bfloat16* Ah = dsm;                   // [8 warps][16 rows][ASTR]
    __nv_bfloat16* Al = Ah + 8*16*ASTR;
    __nv_bfloat16* Bh = Al + 8*16*ASTR;        // [64 c][ASTR]
    __nv_bfloat16* Bl = Bh + 64*ASTR;
    __shared__ float s_sh[TI], Mi_sh[TI], l_sh[TI];

    int tid = threadIdx.x, lane = tid & 31, w = tid >> 5;
    int grp = lane >> 2, qt = lane & 3;        // frag coords
    int b = blockIdx.y, i0 = blockIdx.x * TI;

    if (tid < TI) {
        float s = g_s[b*NN + i0 + tid];
        s_sh[tid] = s;
        float mi = s + g_dmax[b];
        Mi_sh[tid] = mi > 0.f ? mi : 0.2f*mi;
        l_sh[tid] = 0.f;
    }

    float d[8][4];
    #pragma unroll
    for (int nt = 0; nt < 8; nt++)
        #pragma unroll
        for (int q = 0; q < 4; q++) d[nt][q] = 0.f;

    const int* adjb = adj + (size_t)(b*2 + 1) * NN * NN;
    __nv_bfloat16* Aw_h = Ah + w*16*ASTR;
    __nv_bfloat16* Aw_l = Al + w*16*ASTR;

    for (int jt = 0; jt < NN/64; jt++) {
        int j0 = jt * 64;
        __syncthreads();   // prev MMA done reading B; first iter: init visible

        // ---- stage B: WhT hi/lo tile [c][j], 16 bf16 per thread per buffer ----
        {
            int c  = tid >> 2;
            int jo = (tid & 3) * 16;
            size_t src = ((size_t)b*64 + c)*NN + j0 + jo;
            *(uint4*)&Bh[c*ASTR + jo]     = *(const uint4*)&g_WhT_hi[src];
            *(uint4*)&Bh[c*ASTR + jo + 8] = *(const uint4*)&g_WhT_hi[src + 8];
            *(uint4*)&Bl[c*ASTR + jo]     = *(const uint4*)&g_WhT_lo[src];
            *(uint4*)&Bl[c*ASTR + jo + 8] = *(const uint4*)&g_WhT_lo[src + 8];
        }

        // ---- P-phase: warp-private rows; lane owns j = 2*lane, 2*lane+1 ----
        float2 dv = *(const float2*)&g_d[b*NN + j0 + 2*lane];
        #pragma unroll 4
        for (int r = 0; r < 16; r++) {
            int ii = w*16 + r;
            float si = s_sh[ii];
            float mi = Mi_sh[ii];
            int2 av = *(const int2*)&adjb[(size_t)(i0 + ii)*NN + j0 + 2*lane];
            float v0 = si + dv.x, v1 = si + dv.y;
            float e0 = v0 > 0.f ? v0 : 0.2f*v0;
            float e1 = v1 > 0.f ? v1 : 0.2f*v1;
            e0 = av.x > 0 ? e0 : NEGV;
            e1 = av.y > 0 ? e1 : NEGV;
            float p0 = __expf(e0 - mi);
            float p1 = __expf(e1 - mi);
            float psum = p0 + p1;
            #pragma unroll
            for (int o = 16; o > 0; o >>= 1)
                psum += __shfl_xor_sync(0xffffffffu, psum, o);
            if (lane == 0) l_sh[ii] += psum;
            __nv_bfloat16 h0 = __float2bfloat16(p0);
            __nv_bfloat16 h1 = __float2bfloat16(p1);
            __nv_bfloat16 q0 = __float2bfloat16(p0 - __bfloat162float(h0));
            __nv_bfloat16 q1 = __float2bfloat16(p1 - __bfloat162float(h1));
            __nv_bfloat162 hh; hh.x = h0; hh.y = h1;
            __nv_bfloat162 ll; ll.x = q0; ll.y = q1;
            *(__nv_bfloat162*)&Aw_h[r*ASTR + 2*lane] = hh;
            *(__nv_bfloat162*)&Aw_l[r*ASTR + 2*lane] = ll;
        }
        __syncwarp();
        __syncthreads();   // B staged (A warp-private, covered by syncwarp)

        // ---- MMA: 4 k-chunks x 8 n-tiles x 3 passes ----
        #pragma unroll
        for (int kc = 0; kc < 4; kc++) {
            int kb = kc*16 + qt*2;
            uint32_t ah[4], al[4];
            ah[0] = *(const uint32_t*)&Aw_h[grp*ASTR + kb];
            ah[1] = *(const uint32_t*)&Aw_h[(grp+8)*ASTR + kb];
            ah[2] = *(const uint32_t*)&Aw_h[grp*ASTR + kb + 8];
            ah[3] = *(const uint32_t*)&Aw_h[(grp+8)*ASTR + kb + 8];
            al[0] = *(const uint32_t*)&Aw_l[grp*ASTR + kb];
            al[1] = *(const uint32_t*)&Aw_l[(grp+8)*ASTR + kb];
            al[2] = *(const uint32_t*)&Aw_l[grp*ASTR + kb + 8];
            al[3] = *(const uint32_t*)&Aw_l[(grp+8)*ASTR + kb + 8];
            #pragma unroll
            for (int nt = 0; nt < 8; nt++) {
                int n = nt*8 + grp;
                uint32_t bh0 = *(const uint32_t*)&Bh[n*ASTR + kb];
                uint32_t bh1 = *(const uint32_t*)&Bh[n*ASTR + kb + 8];
                uint32_t bl0 = *(const uint32_t*)&Bl[n*ASTR + kb];
                uint32_t bl1 = *(const uint32_t*)&Bl[n*ASTR + kb + 8];
                mma16816(d[nt], ah, bh0, bh1);
                mma16816(d[nt], al, bh0, bh1);
                mma16816(d[nt], ah, bl0, bl1);
            }
        }
    }

    // ---- epilogue: scale rows by 1/l, elu, store ----
    float l0 = l_sh[w*16 + grp];
    float l1 = l_sh[w*16 + grp + 8];
    if (!(l0 > 0.f)) l0 = 1.f;
    if (!(l1 > 0.f)) l1 = 1.f;
    float inv0 = 1.f / l0, inv1 = 1.f / l1;
    size_t ob0 = ((size_t)b*NN + i0 + w*16 + grp)    *HH2;
    size_t ob1 = ((size_t)b*NN + i0 + w*16 + grp + 8)*HH2;
    #pragma unroll
    for (int nt = 0; nt < 8; nt++) {
        int col = nt*8 + qt*2;
        float z0 = d[nt][0]*inv0, z1 = d[nt][1]*inv0;
        float z2 = d[nt][2]*inv1, z3 = d[nt][3]*inv1;
        z0 = z0 > 0.f ? z0 : expm1f(z0);
        z1 = z1 > 0.f ? z1 : expm1f(z1);
        z2 = z2 > 0.f ? z2 : expm1f(z2);
        z3 = z3 > 0.f ? z3 : expm1f(z3);
        *(float2*)&out[ob0 + col] = make_float2(z0, z1);
        *(float2*)&out[ob1 + col] = make_float2(z2, z3);
    }
}

// ============================================================================
extern "C" void kernel_launch(void* const* d_in, const int* in_sizes, int n_in,
                              void* d_out, int out_size) {
    const float* hist  = (const float*)d_in[0];
    const int*   adj   = (const int*)  d_in[1];
    const float* W1    = (const float*)d_in[2];
    const float* b1    = (const float*)d_in[3];
    const float* W_ih  = (const float*)d_in[4];
    const float* W_hh  = (const float*)d_in[5];
    const float* b_ih  = (const float*)d_in[6];
    const float* b_hh  = (const float*)d_in[7];
    const float* Wg    = (const float*)d_in[8];
    const float* a_src = (const float*)d_in[9];
    const float* a_dst = (const float*)d_in[10];
    float* out = (float*)d_out;

    const size_t sm_lstm = (size_t)(64*256 + 64*21) * sizeof(float);
    const size_t sm_gat  = (size_t)(2*8*16*ASTR + 2*64*ASTR) * sizeof(__nv_bfloat16);
    cudaFuncSetAttribute(k_lstm2, cudaFuncAttributeMaxDynamicSharedMemorySize, (int)sm_lstm);
    cudaFuncSetAttribute(k_gat,   cudaFuncAttributeMaxDynamicSharedMemorySize, (int)sm_gat);

    k_h1   <<<2048, 256>>>(hist, W1, b1);
    k_wx   <<<2048, 256>>>(W_ih, b_ih, b_hh);
    k_lstm2<<<128,  256, sm_lstm>>>(W_hh);
    k_wh   <<<1024, 256>>>(Wg, a_src, a_dst);
    dim3 gt(NN/64, BB);
    k_trans<<<gt, 256>>>();
    k_dmax <<<BB, 256>>>();
    dim3 g4(NN/TI, BB);
    k_gat  <<<g4, 256, sm_gat>>>(adj, out);
}

// round 7
// speedup vs baseline: 1.4909x; 1.4909x over previous
#include <cuda_runtime.h>
#include <math.h>
#include <stdint.h>

typedef unsigned long long ull;

#define BB   8
#define FHH  8
#define NN   2048
#define TINN 5
#define HH1  32
#define HH2  64
#define KXX  40
#define TI2  256          // gat rows per CTA
#define PS2  258          // PsT row stride (floats)
#define SPLIT 4
#define ROWS_TOT (BB*NN)

// ---------------- scratch ----------------------------------------------------
__device__ float g_h1[BB*NN*HH1];
__device__ float g_wx[BB*NN*4*HH2];
__device__ float g_hs[BB*NN*HH2];
__device__ float g_Wh[BB*NN*HH2];
__device__ float g_s [BB*NN];
__device__ float g_d [BB*NN];
__device__ float g_dmax[BB];
__device__ float g_pl  [SPLIT*ROWS_TOT];
__device__ float g_pacc[SPLIT*ROWS_TOT*HH2];

// ---------------- f32x2 helpers ----------------------------------------------
__device__ __forceinline__ ull pack2(float lo, float hi) {
    ull r; asm("mov.b64 %0, {%1, %2};" : "=l"(r) : "f"(lo), "f"(hi)); return r;
}
__device__ __forceinline__ void unpack2(ull v, float& lo, float& hi) {
    asm("mov.b64 {%0, %1}, %2;" : "=f"(lo), "=f"(hi) : "l"(v));
}
__device__ __forceinline__ ull ffma2(ull a, ull b, ull c) {
    ull r; asm("fma.rn.f32x2 %0, %1, %2, %3;" : "=l"(r) : "l"(a), "l"(b), "l"(c)); return r;
}
__device__ __forceinline__ float fsig(float x) { return __fdividef(1.f, 1.f + __expf(-x)); }
__device__ __forceinline__ float ftanh(float x) {
    return fmaf(__fdividef(2.f, 1.f + __expf(-2.f*x)), 1.f, -1.f);
}

// ============================================================================
// Kernel 1: h1 = elu(x @ W1^T + b1). Coalesced hist reads.
// grid (32, 8): n-chunk of 64 nodes x time t. 256 threads.
// ============================================================================
__global__ void k_h1(const float* __restrict__ hist,
                     const float* __restrict__ W1,
                     const float* __restrict__ b1) {
    __shared__ float xs[KXX*66];      // [k=tt*8+f][n] pad 66
    __shared__ float w1s[KXX*HH1];    // [j][k_out]
    int tid = threadIdx.x;
    int n0 = blockIdx.x * 64;
    int t  = blockIdx.y;
    // hist[t, f, n0..n0+63, tt]: per f a contiguous 320-float segment
    for (int i = tid; i < FHH*64*TINN; i += 256) {
        int f = i / 320, rem = i % 320;
        int n = rem / TINN, tt = rem % TINN;
        xs[(tt*FHH + f)*66 + n] = hist[((size_t)(t*FHH + f)*NN + n0)*TINN + rem];
    }
    for (int i = tid; i < HH1*KXX; i += 256) {
        int k = i / KXX, j = i % KXX;
        w1s[j*HH1 + k] = W1[i];
    }
    __syncthreads();
    int k  = tid & 31;                // output unit (coalesced stores)
    int ng = tid >> 5;                // 8 node groups of 8
    float bb = b1[k];
    #pragma unroll
    for (int q = 0; q < 8; q++) {
        int n = ng*8 + q;
        float acc = bb;
        #pragma unroll 8
        for (int j = 0; j < KXX; j++)
            acc = fmaf(xs[j*66 + n], w1s[j*HH1 + k], acc);
        acc = acc > 0.f ? acc : expm1f(acc);
        g_h1[(size_t)(t*NN + n0 + n)*HH1 + k] = acc;
    }
}

// ============================================================================
// Kernel 1b: wx = h1 @ W_ih^T + (b_ih+b_hh), interleaved [u*4+gt]
// ============================================================================
__global__ void k_wx(const float* __restrict__ W_ih,
                     const float* __restrict__ b_ih, const float* __restrict__ b_hh) {
    __shared__ float wih[HH1*256];
    __shared__ float bsI[256];
    __shared__ float h1s[HH1*9];
    int tid = threadIdx.x;
    int row0 = blockIdx.x * 8;
    for (int i = tid; i < HH1*256; i += 256) {
        int j = i >> 8, op = i & 255, u = op >> 2, gt = op & 3;
        wih[i] = W_ih[(gt*64 + u)*HH1 + j];
    }
    { int u = tid >> 2, gt = tid & 3; bsI[tid] = b_ih[gt*64+u] + b_hh[gt*64+u]; }
    { int r = tid & 7, j = tid >> 3; h1s[j*9 + r] = g_h1[(row0 + r)*HH1 + j]; }
    __syncthreads();

    int u  = tid & 63;
    int r0 = (tid >> 6) * 2;
    ull acc[2][2];
    ull b0 = *(const ull*)&bsI[u*4], b1v = *(const ull*)&bsI[u*4+2];
    acc[0][0]=b0; acc[0][1]=b1v; acc[1][0]=b0; acc[1][1]=b1v;
    #pragma unroll 8
    for (int j = 0; j < HH1; j++) {
        ulonglong2 wv = *(const ulonglong2*)&wih[j*256 + u*4];
        float ha = h1s[j*9 + r0], hb = h1s[j*9 + r0 + 1];
        ull ha2 = pack2(ha, ha), hb2 = pack2(hb, hb);
        acc[0][0] = ffma2(wv.x, ha2, acc[0][0]);
        acc[0][1] = ffma2(wv.y, ha2, acc[0][1]);
        acc[1][0] = ffma2(wv.x, hb2, acc[1][0]);
        acc[1][1] = ffma2(wv.y, hb2, acc[1][1]);
    }
    #pragma unroll
    for (int nd = 0; nd < 2; nd++) {
        float v0,v1,v2,v3;
        unpack2(acc[nd][0], v0, v1);
        unpack2(acc[nd][1], v2, v3);
        *(float4*)&g_wx[(size_t)(row0 + r0 + nd)*256 + u*4] = make_float4(v0,v1,v2,v3);
    }
}

// ============================================================================
// Kernel 2: recurrent LSTM (W_hh part only)
// ============================================================================
__global__ void __launch_bounds__(256) k_lstm2(const float* __restrict__ W_hh) {
    extern __shared__ float sm[];
    float* whh = sm;
    float* hsh = whh + 64*256;

    int tid = threadIdx.x;
    for (int i = tid; i < 64*256; i += 256) {
        int j = i >> 8, op = i & 255, u = op >> 2, gt = op & 3;
        whh[i] = W_hh[(gt*64 + u)*HH2 + j];
    }
    for (int i = tid; i < 64*21; i += 256) hsh[i] = 0.f;

    int u  = tid & 63;
    int nq = tid >> 6;
    int node0 = blockIdx.x * 16 + nq*4;

    float c[4] = {0.f,0.f,0.f,0.f};
    float4 wx4[4];
    #pragma unroll
    for (int n = 0; n < 4; n++)
        wx4[n] = *(const float4*)&g_wx[(size_t)(node0 + n)*256 + u*4];

    for (int t = 0; t < BB; t++) {
        __syncthreads();
        ull acc[4][2];
        #pragma unroll
        for (int n = 0; n < 4; n++) {
            acc[n][0] = pack2(wx4[n].x, wx4[n].y);
            acc[n][1] = pack2(wx4[n].z, wx4[n].w);
        }
        if (t < BB-1) {
            #pragma unroll
            for (int n = 0; n < 4; n++)
                wx4[n] = *(const float4*)&g_wx[(size_t)((t+1)*NN + node0 + n)*256 + u*4];
        }
        #pragma unroll 4
        for (int j = 0; j < HH2; j++) {
            ulonglong2 wv = *(const ulonglong2*)&whh[j*256 + u*4];
            #pragma unroll
            for (int n = 0; n < 4; n++) {
                float hv = hsh[j*21 + nq*4 + n];
                ull hv2 = pack2(hv, hv);
                acc[n][0] = ffma2(wv.x, hv2, acc[n][0]);
                acc[n][1] = ffma2(wv.y, hv2, acc[n][1]);
            }
        }
        __syncthreads();
        #pragma unroll
        for (int n = 0; n < 4; n++) {
            float gi,gf,gg,go;
            unpack2(acc[n][0], gi, gf);
            unpack2(acc[n][1], gg, go);
            c[n] = fsig(gf)*c[n] + fsig(gi)*ftanh(gg);
            float h = fsig(go)*ftanh(c[n]);
            hsh[u*21 + nq*4 + n] = h;
            g_hs[(size_t)(t*NN + node0 + n)*HH2 + u] = h;
        }
    }
}

// ============================================================================
// Kernel 3: Wh = hs @ Wg ; s = Wh.a_src ; d = Wh.a_dst
// ============================================================================
__global__ void k_wh(const float* __restrict__ Wg,
                     const float* __restrict__ a_src,
                     const float* __restrict__ a_dst) {
    __shared__ float wgs[64*64];
    __shared__ float hss[64*17];
    __shared__ float ps[16*17];
    __shared__ float pd[16*17];
    int tid = threadIdx.x;
    int row0 = blockIdx.x * 16;
    for (int i = tid; i < 4096; i += 256) wgs[i] = Wg[i];
    for (int i = tid; i < 1024; i += 256) {
        int mm = i >> 6, u = i & 63;
        hss[u*17 + mm] = g_hs[(row0 + mm)*HH2 + u];
    }
    __syncthreads();
    int m  = tid >> 4;
    int cq = tid & 15;
    int c0 = cq * 4;
    ull acc0 = 0ull, acc1 = 0ull;
    #pragma unroll 8
    for (int u = 0; u < 64; u++) {
        float hv = hss[u*17 + m];
        ull hv2 = pack2(hv, hv);
        acc0 = ffma2(*(const ull*)&wgs[u*64 + c0],     hv2, acc0);
        acc1 = ffma2(*(const ull*)&wgs[u*64 + c0 + 2], hv2, acc1);
    }
    float wh[4];
    unpack2(acc0, wh[0], wh[1]);
    unpack2(acc1, wh[2], wh[3]);
    *(float4*)&g_Wh[(row0 + m)*HH2 + c0] = make_float4(wh[0], wh[1], wh[2], wh[3]);
    float psum = 0.f, dsum = 0.f;
    #pragma unroll
    for (int q = 0; q < 4; q++) {
        psum = fmaf(wh[q], a_src[c0 + q], psum);
        dsum = fmaf(wh[q], a_dst[c0 + q], dsum);
    }
    ps[m*17 + cq] = psum;
    pd[m*17 + cq] = dsum;
    __syncthreads();
    if (tid < 16) {
        float s = 0.f, d = 0.f;
        #pragma unroll
        for (int q = 0; q < 16; q++) { s += ps[tid*17 + q]; d += pd[tid*17 + q]; }
        g_s[row0 + tid] = s;
        g_d[row0 + tid] = d;
    }
}

// ============================================================================
// Kernel 3c: per-batch max of d
// ============================================================================
__global__ void k_dmax() {
    __shared__ float red[8];
    int b = blockIdx.x, tid = threadIdx.x;
    float m = -1e30f;
    for (int i = tid; i < NN; i += 256) m = fmaxf(m, g_d[b*NN + i]);
    #pragma unroll
    for (int o = 16; o > 0; o >>= 1)
        m = fmaxf(m, __shfl_xor_sync(0xffffffffu, m, o));
    if ((tid & 31) == 0) red[tid >> 5] = m;
    __syncthreads();
    if (tid == 0) {
        float mm = red[0];
        #pragma unroll
        for (int q = 1; q < 8; q++) mm = fmaxf(mm, red[q]);
        g_dmax[b] = mm;
    }
}

// ============================================================================
// Kernel 4: GAT, exp-free P-phase + 8x8 register-tile f32x2 GEMM.
//   exp(lrelu(s_i+d_j)-M_i) = (s_i+d_j>0) ? Ap_i*bp_j : An_i*bm_j, all <= 1.
//   Fixed shift M_i = lrelu(s_i + dmax_b) => split-K partials purely additive.
// grid (8, 8, SPLIT), 256 thr, 2 CTA/SM. Per thread: 8 rows x 8 cols.
// ============================================================================
__global__ void __launch_bounds__(256, 2) k_gat(const int* __restrict__ adj) {
    extern __shared__ char smraw[];
    ull*   whs = (ull*)smraw;                      // [jj][c] dup pairs, 32KB
    float* PsT = (float*)(smraw + 64*64*8);        // [jj][ii] stride PS2, 66KB
    __shared__ float thr_sh[TI2], Ap_sh[TI2], An_sh[TI2], l_sh[TI2];

    int tid = threadIdx.x, lane = tid & 31, w = tid >> 5;
    int b = blockIdx.y, i0 = blockIdx.x * TI2, sp = blockIdx.z;

    float dmax = g_dmax[b];
    {
        float s = g_s[b*NN + i0 + tid];
        float sm = s + dmax;
        float M = sm > 0.f ? sm : 0.2f*sm;
        Ap_sh[tid]  = __expf(sm - M);
        An_sh[tid]  = __expf(0.2f*sm - M);
        thr_sh[tid] = -s;
        l_sh[tid]   = 0.f;
    }

    int rg  = tid >> 3;      // 32 row groups x 8 rows
    int cgp = tid & 7;       // cols cgp + 8k
    ull acc[4][8];
    #pragma unroll
    for (int rp = 0; rp < 4; rp++)
        #pragma unroll
        for (int k = 0; k < 8; k++) acc[rp][k] = 0ull;

    const int* adjb = adj + (size_t)(b*2 + 1) * NN * NN;
    const int JT = (NN/64)/SPLIT;

    for (int jtl = 0; jtl < JT; jtl++) {
        int j0 = (sp * JT + jtl) * 64;
        __syncthreads();                 // prev GEMM done reading smem

        for (int i = tid; i < 4096; i += 256) {
            int jj = i >> 6, c = i & 63;
            float v = g_Wh[(size_t)(b*NN + j0 + jj)*64 + c];
            whs[jj*64 + c] = pack2(v, v);
        }
        float2 dv = *(const float2*)&g_d[b*NN + j0 + 2*lane];
        float bp0 = __expf(dv.x - dmax);
        float bp1 = __expf(dv.y - dmax);
        float bm0 = __expf(0.2f*(dv.x - dmax));
        float bm1 = __expf(0.2f*(dv.y - dmax));

        #pragma unroll 4
        for (int r = 0; r < 32; r++) {
            int ii = w*32 + r;
            float thr = thr_sh[ii], Ap = Ap_sh[ii], An = An_sh[ii];
            int2 av = *(const int2*)&adjb[(size_t)(i0 + ii)*NN + j0 + 2*lane];
            float c0 = (dv.x > thr) ? Ap*bp0 : An*bm0;
            float c1 = (dv.y > thr) ? Ap*bp1 : An*bm1;
            c0 = av.x > 0 ? c0 : 0.f;
            c1 = av.y > 0 ? c1 : 0.f;
            float psum = c0 + c1;
            #pragma unroll
            for (int o = 16; o > 0; o >>= 1)
                psum += __shfl_xor_sync(0xffffffffu, psum, o);
            if (lane == 0) l_sh[ii] += psum;
            PsT[(2*lane)*PS2   + ii] = c0;
            PsT[(2*lane+1)*PS2 + ii] = c1;
        }
        __syncthreads();

        const float* pbase = PsT + rg*8;
        const ull*   wbase = whs + cgp;
        #pragma unroll 2
        for (int jj = 0; jj < 64; jj++) {
            ull wd[8];
            #pragma unroll
            for (int k = 0; k < 8; k++) wd[k] = wbase[jj*64 + 8*k];
            ull pp[4];
            #pragma unroll
            for (int rp = 0; rp < 4; rp++)
                pp[rp] = *(const ull*)&pbase[jj*PS2 + 2*rp];
            #pragma unroll
            for (int rp = 0; rp < 4; rp++)
                #pragma unroll
                for (int k = 0; k < 8; k++)
                    acc[rp][k] = ffma2(wd[k], pp[rp], acc[rp][k]);
        }
    }
    __syncthreads();

    g_pl[sp*ROWS_TOT + b*NN + i0 + tid] = l_sh[tid];
    #pragma unroll
    for (int rp = 0; rp < 4; rp++) {
        int r0 = rg*8 + 2*rp;
        size_t base0 = ((size_t)sp*ROWS_TOT + b*NN + i0 + r0)     * HH2;
        size_t base1 = ((size_t)sp*ROWS_TOT + b*NN + i0 + r0 + 1) * HH2;
        #pragma unroll
        for (int k = 0; k < 8; k++) {
            float va, vb;
            unpack2(acc[rp][k], va, vb);
            g_pacc[base0 + cgp + 8*k] = va;
            g_pacc[base1 + cgp + 8*k] = vb;
        }
    }
}

// ============================================================================
// Kernel 5: combine additive split-K partials; normalize + elu.
// ============================================================================
__global__ void k_comb(float* __restrict__ out) {
    int tid = threadIdx.x;
    int r = blockIdx.x * 4 + (tid >> 6);
    int c = tid & 63;
    float l = 0.f, val = 0.f;
    #pragma unroll
    for (int s = 0; s < SPLIT; s++) {
        l   += g_pl[s*ROWS_TOT + r];
        val += g_pacc[((size_t)s*ROWS_TOT + r)*HH2 + c];
    }
    float z = val / l;
    out[(size_t)r*HH2 + c] = z > 0.f ? z : expm1f(z);
}

// ============================================================================
extern "C" void kernel_launch(void* const* d_in, const int* in_sizes, int n_in,
                              void* d_out, int out_size) {
    const float* hist  = (const float*)d_in[0];
    const int*   adj   = (const int*)  d_in[1];
    const float* W1    = (const float*)d_in[2];
    const float* b1    = (const float*)d_in[3];
    const float* W_ih  = (const float*)d_in[4];
    const float* W_hh  = (const float*)d_in[5];
    const float* b_ih  = (const float*)d_in[6];
    const float* b_hh  = (const float*)d_in[7];
    const float* Wg    = (const float*)d_in[8];
    const float* a_src = (const float*)d_in[9];
    const float* a_dst = (const float*)d_in[10];
    float* out = (float*)d_out;

    const size_t sm_lstm = (size_t)(64*256 + 64*21) * sizeof(float);
    const size_t sm_gat  = (size_t)(64*64*8) + (size_t)(64*PS2*4);
    cudaFuncSetAttribute(k_lstm2, cudaFuncAttributeMaxDynamicSharedMemorySize, (int)sm_lstm);
    cudaFuncSetAttribute(k_gat,   cudaFuncAttributeMaxDynamicSharedMemorySize, (int)sm_gat);

    dim3 g1(32, 8);
    k_h1   <<<g1, 256>>>(hist, W1, b1);
    k_wx   <<<2048, 256>>>(W_ih, b_ih, b_hh);
    k_lstm2<<<128,  256, sm_lstm>>>(W_hh);
    k_wh   <<<1024, 256>>>(Wg, a_src, a_dst);
    k_dmax <<<BB, 256>>>();
    dim3 g4(NN/TI2, BB, SPLIT);
    k_gat  <<<g4, 256, sm_gat>>>(adj);
    k_comb <<<4096, 256>>>(out);
}

// round 8
// speedup vs baseline: 1.6039x; 1.0758x over previous
#include <cuda_runtime.h>
#include <math.h>
#include <stdint.h>

typedef unsigned long long ull;

#define BB   8
#define FHH  8
#define NN   2048
#define TINN 5
#define HH1  32
#define HH2  64
#define KXX  40
#define TI   128
#define PS   130          // PsT row stride (floats)
#define SPLIT 8
#define ROWS_TOT (BB*NN)

// ---------------- scratch ----------------------------------------------------
__device__ float g_h1[BB*NN*HH1];
__device__ float g_wx[BB*NN*4*HH2];
__device__ float g_hs[BB*NN*HH2];
__device__ float g_Wh[BB*NN*HH2];
__device__ float g_s [BB*NN];
__device__ float g_d [BB*NN];
__device__ float g_dmax[BB];
__device__ float g_pl  [SPLIT*ROWS_TOT];
__device__ float g_pacc[SPLIT*ROWS_TOT*HH2];

// ---------------- f32x2 helpers ----------------------------------------------
__device__ __forceinline__ ull pack2(float lo, float hi) {
    ull r; asm("mov.b64 %0, {%1, %2};" : "=l"(r) : "f"(lo), "f"(hi)); return r;
}
__device__ __forceinline__ void unpack2(ull v, float& lo, float& hi) {
    asm("mov.b64 {%0, %1}, %2;" : "=f"(lo), "=f"(hi) : "l"(v));
}
__device__ __forceinline__ ull ffma2(ull a, ull b, ull c) {
    ull r; asm("fma.rn.f32x2 %0, %1, %2, %3;" : "=l"(r) : "l"(a), "l"(b), "l"(c)); return r;
}
__device__ __forceinline__ ull fadd2(ull a, ull b) {
    ull r; asm("add.rn.f32x2 %0, %1, %2;" : "=l"(r) : "l"(a), "l"(b)); return r;
}
__device__ __forceinline__ float fsig(float x) { return __fdividef(1.f, 1.f + __expf(-x)); }
__device__ __forceinline__ float ftanh(float x) {
    return fmaf(__fdividef(2.f, 1.f + __expf(-2.f*x)), 1.f, -1.f);
}

// ============================================================================
// Kernel 1: h1 = elu(x @ W1^T + b1). Coalesced hist reads.
// ============================================================================
__global__ void k_h1(const float* __restrict__ hist,
                     const float* __restrict__ W1,
                     const float* __restrict__ b1) {
    __shared__ float xs[KXX*66];
    __shared__ float w1s[KXX*HH1];
    int tid = threadIdx.x;
    int n0 = blockIdx.x * 64;
    int t  = blockIdx.y;
    for (int i = tid; i < FHH*64*TINN; i += 256) {
        int f = i / 320, rem = i % 320;
        int n = rem / TINN, tt = rem % TINN;
        xs[(tt*FHH + f)*66 + n] = hist[((size_t)(t*FHH + f)*NN + n0)*TINN + rem];
    }
    for (int i = tid; i < HH1*KXX; i += 256) {
        int k = i / KXX, j = i % KXX;
        w1s[j*HH1 + k] = W1[i];
    }
    __syncthreads();
    int k  = tid & 31;
    int ng = tid >> 5;
    float bb = b1[k];
    #pragma unroll
    for (int q = 0; q < 8; q++) {
        int n = ng*8 + q;
        float acc = bb;
        #pragma unroll 8
        for (int j = 0; j < KXX; j++)
            acc = fmaf(xs[j*66 + n], w1s[j*HH1 + k], acc);
        acc = acc > 0.f ? acc : expm1f(acc);
        g_h1[(size_t)(t*NN + n0 + n)*HH1 + k] = acc;
    }
}

// ============================================================================
// Kernel 1b: wx = h1 @ W_ih^T + (b_ih+b_hh), interleaved [u*4+gt]
// ============================================================================
__global__ void k_wx(const float* __restrict__ W_ih,
                     const float* __restrict__ b_ih, const float* __restrict__ b_hh) {
    __shared__ float wih[HH1*256];
    __shared__ float bsI[256];
    __shared__ float h1s[HH1*9];
    int tid = threadIdx.x;
    int row0 = blockIdx.x * 8;
    for (int i = tid; i < HH1*256; i += 256) {
        int j = i >> 8, op = i & 255, u = op >> 2, gt = op & 3;
        wih[i] = W_ih[(gt*64 + u)*HH1 + j];
    }
    { int u = tid >> 2, gt = tid & 3; bsI[tid] = b_ih[gt*64+u] + b_hh[gt*64+u]; }
    { int r = tid & 7, j = tid >> 3; h1s[j*9 + r] = g_h1[(row0 + r)*HH1 + j]; }
    __syncthreads();

    int u  = tid & 63;
    int r0 = (tid >> 6) * 2;
    ull acc[2][2];
    ull b0 = *(const ull*)&bsI[u*4], b1v = *(const ull*)&bsI[u*4+2];
    acc[0][0]=b0; acc[0][1]=b1v; acc[1][0]=b0; acc[1][1]=b1v;
    #pragma unroll 8
    for (int j = 0; j < HH1; j++) {
        ulonglong2 wv = *(const ulonglong2*)&wih[j*256 + u*4];
        float ha = h1s[j*9 + r0], hb = h1s[j*9 + r0 + 1];
        ull ha2 = pack2(ha, ha), hb2 = pack2(hb, hb);
        acc[0][0] = ffma2(wv.x, ha2, acc[0][0]);
        acc[0][1] = ffma2(wv.y, ha2, acc[0][1]);
        acc[1][0] = ffma2(wv.x, hb2, acc[1][0]);
        acc[1][1] = ffma2(wv.y, hb2, acc[1][1]);
    }
    #pragma unroll
    for (int nd = 0; nd < 2; nd++) {
        float v0,v1,v2,v3;
        unpack2(acc[nd][0], v0, v1);
        unpack2(acc[nd][1], v2, v3);
        *(float4*)&g_wx[(size_t)(row0 + r0 + nd)*256 + u*4] = make_float4(v0,v1,v2,v3);
    }
}

// ============================================================================
// Kernel 2: recurrent LSTM (W_hh part only)
// ============================================================================
__global__ void __launch_bounds__(256) k_lstm2(const float* __restrict__ W_hh) {
    extern __shared__ float sm[];
    float* whh = sm;
    float* hsh = whh + 64*256;

    int tid = threadIdx.x;
    for (int i = tid; i < 64*256; i += 256) {
        int j = i >> 8, op = i & 255, u = op >> 2, gt = op & 3;
        whh[i] = W_hh[(gt*64 + u)*HH2 + j];
    }
    for (int i = tid; i < 64*21; i += 256) hsh[i] = 0.f;

    int u  = tid & 63;
    int nq = tid >> 6;
    int node0 = blockIdx.x * 16 + nq*4;

    float c[4] = {0.f,0.f,0.f,0.f};
    float4 wx4[4];
    #pragma unroll
    for (int n = 0; n < 4; n++)
        wx4[n] = *(const float4*)&g_wx[(size_t)(node0 + n)*256 + u*4];

    for (int t = 0; t < BB; t++) {
        __syncthreads();
        ull acc[4][2];
        #pragma unroll
        for (int n = 0; n < 4; n++) {
            acc[n][0] = pack2(wx4[n].x, wx4[n].y);
            acc[n][1] = pack2(wx4[n].z, wx4[n].w);
        }
        if (t < BB-1) {
            #pragma unroll
            for (int n = 0; n < 4; n++)
                wx4[n] = *(const float4*)&g_wx[(size_t)((t+1)*NN + node0 + n)*256 + u*4];
        }
        #pragma unroll 4
        for (int j = 0; j < HH2; j++) {
            ulonglong2 wv = *(const ulonglong2*)&whh[j*256 + u*4];
            #pragma unroll
            for (int n = 0; n < 4; n++) {
                float hv = hsh[j*21 + nq*4 + n];
                ull hv2 = pack2(hv, hv);
                acc[n][0] = ffma2(wv.x, hv2, acc[n][0]);
                acc[n][1] = ffma2(wv.y, hv2, acc[n][1]);
            }
        }
        __syncthreads();
        #pragma unroll
        for (int n = 0; n < 4; n++) {
            float gi,gf,gg,go;
            unpack2(acc[n][0], gi, gf);
            unpack2(acc[n][1], gg, go);
            c[n] = fsig(gf)*c[n] + fsig(gi)*ftanh(gg);
            float h = fsig(go)*ftanh(c[n]);
            hsh[u*21 + nq*4 + n] = h;
            g_hs[(size_t)(t*NN + node0 + n)*HH2 + u] = h;
        }
    }
}

// ============================================================================
// Kernel 3: Wh = hs @ Wg ; s = Wh.a_src ; d = Wh.a_dst
// ============================================================================
__global__ void k_wh(const float* __restrict__ Wg,
                     const float* __restrict__ a_src,
                     const float* __restrict__ a_dst) {
    __shared__ float wgs[64*64];
    __shared__ float hss[64*17];
    __shared__ float ps[16*17];
    __shared__ float pd[16*17];
    int tid = threadIdx.x;
    int row0 = blockIdx.x * 16;
    for (int i = tid; i < 4096; i += 256) wgs[i] = Wg[i];
    for (int i = tid; i < 1024; i += 256) {
        int mm = i >> 6, u = i & 63;
        hss[u*17 + mm] = g_hs[(row0 + mm)*HH2 + u];
    }
    __syncthreads();
    int m  = tid >> 4;
    int cq = tid & 15;
    int c0 = cq * 4;
    ull acc0 = 0ull, acc1 = 0ull;
    #pragma unroll 8
    for (int u = 0; u < 64; u++) {
        float hv = hss[u*17 + m];
        ull hv2 = pack2(hv, hv);
        acc0 = ffma2(*(const ull*)&wgs[u*64 + c0],     hv2, acc0);
        acc1 = ffma2(*(const ull*)&wgs[u*64 + c0 + 2], hv2, acc1);
    }
    float wh[4];
    unpack2(acc0, wh[0], wh[1]);
    unpack2(acc1, wh[2], wh[3]);
    *(float4*)&g_Wh[(row0 + m)*HH2 + c0] = make_float4(wh[0], wh[1], wh[2], wh[3]);
    float psum = 0.f, dsum = 0.f;
    #pragma unroll
    for (int q = 0; q < 4; q++) {
        psum = fmaf(wh[q], a_src[c0 + q], psum);
        dsum = fmaf(wh[q], a_dst[c0 + q], dsum);
    }
    ps[m*17 + cq] = psum;
    pd[m*17 + cq] = dsum;
    __syncthreads();
    if (tid < 16) {
        float s = 0.f, d = 0.f;
        #pragma unroll
        for (int q = 0; q < 16; q++) { s += ps[tid*17 + q]; d += pd[tid*17 + q]; }
        g_s[row0 + tid] = s;
        g_d[row0 + tid] = d;
    }
}

// ============================================================================
// Kernel 3c: per-batch max of d
// ============================================================================
__global__ void k_dmax() {
    __shared__ float red[8];
    int b = blockIdx.x, tid = threadIdx.x;
    float m = -1e30f;
    for (int i = tid; i < NN; i += 256) m = fmaxf(m, g_d[b*NN + i]);
    #pragma unroll
    for (int o = 16; o > 0; o >>= 1)
        m = fmaxf(m, __shfl_xor_sync(0xffffffffu, m, o));
    if ((tid & 31) == 0) red[tid >> 5] = m;
    __syncthreads();
    if (tid == 0) {
        float mm = red[0];
        #pragma unroll
        for (int q = 1; q < 8; q++) mm = fmaxf(mm, red[q]);
        g_dmax[b] = mm;
    }
}

// ============================================================================
// Kernel 4: GAT. Exp-free P-phase (rank-1 factorization, fixed shift),
// NO shuffle reductions (l accumulated inside GEMM via fadd2), adj loads
// front-batched 8 rows deep for MLP. grid (16, 8, SPLIT), 256 thr.
// Thread GEMM tile 4 rows x 8 cols; per jj: 10 LDS.64 + 2 add2 + 16 ffma2.
// ============================================================================
__global__ void __launch_bounds__(256) k_gat(const int* __restrict__ adj) {
    extern __shared__ char smraw[];
    ull*   whs = (ull*)smraw;                      // [jj][c] dup pairs, 32KB
    float* PsT = (float*)(smraw + 64*64*8);        // [jj][ii] stride PS, 33.3KB
    __shared__ float4 row_sh[TI];                  // (thr, Ap, An, -)

    int tid = threadIdx.x, lane = tid & 31, w = tid >> 5;
    int b = blockIdx.y, i0 = blockIdx.x * TI, sp = blockIdx.z;

    float dmax = g_dmax[b];
    if (tid < TI) {
        float s = g_s[b*NN + i0 + tid];
        float sm = s + dmax;
        float M = sm > 0.f ? sm : 0.2f*sm;
        row_sh[tid] = make_float4(-s, __expf(sm - M), __expf(0.2f*sm - M), 0.f);
    }

    int rg  = tid >> 3;      // 32 row groups x 4 rows
    int cgp = tid & 7;       // cols cgp + 8k
    ull acc[2][8];
    #pragma unroll
    for (int rp = 0; rp < 2; rp++)
        #pragma unroll
        for (int k = 0; k < 8; k++) acc[rp][k] = 0ull;
    ull lacc0 = 0ull, lacc1 = 0ull;

    const int* adjb = adj + (size_t)(b*2 + 1) * NN * NN;
    const int JT = (NN/64)/SPLIT;

    for (int jtl = 0; jtl < JT; jtl++) {
        int j0 = (sp * JT + jtl) * 64;
        __syncthreads();                 // prev GEMM done reading smem

        // stage Wh tile as duplicated pairs (float2 loads)
        for (int i = tid; i < 2048; i += 256) {
            float2 v = *(const float2*)&g_Wh[(size_t)(b*NN + j0)*64 + 2*i];
            whs[2*i]   = pack2(v.x, v.x);
            whs[2*i+1] = pack2(v.y, v.y);
        }

        // lane owns j-cols {lane, lane+32}
        float d0 = g_d[b*NN + j0 + lane];
        float d1 = g_d[b*NN + j0 + lane + 32];
        float bp0 = __expf(d0 - dmax);
        float bp1 = __expf(d1 - dmax);
        float bm0 = __expf(0.2f*(d0 - dmax));
        float bm1 = __expf(0.2f*(d1 - dmax));

        // P-phase: warp w -> rows w*16..w*16+15, two batches of 8
        #pragma unroll
        for (int half = 0; half < 2; half++) {
            const int* ab = adjb + (size_t)(i0 + w*16 + half*8)*NN + j0;
            int a0[8], a1[8];
            #pragma unroll
            for (int q = 0; q < 8; q++) {
                a0[q] = ab[(size_t)q*NN + lane];
                a1[q] = ab[(size_t)q*NN + lane + 32];
            }
            #pragma unroll
            for (int q = 0; q < 8; q++) {
                int ii = w*16 + half*8 + q;
                float4 rs = row_sh[ii];
                float c0 = (d0 > rs.x) ? rs.y*bp0 : rs.z*bm0;
                float c1 = (d1 > rs.x) ? rs.y*bp1 : rs.z*bm1;
                c0 = a0[q] > 0 ? c0 : 0.f;
                c1 = a1[q] > 0 ? c1 : 0.f;
                PsT[lane*PS + ii]        = c0;
                PsT[(lane+32)*PS + ii]   = c1;
            }
        }
        __syncthreads();

        // GEMM: rows rg*4 + {0..3} (as 2 ull pairs), cols cgp + 8k
        const float* pbase = PsT + rg*4;
        const ull*   wbase = whs + cgp;
        #pragma unroll 2
        for (int jj = 0; jj < 64; jj++) {
            ull pp0 = *(const ull*)&pbase[jj*PS];
            ull pp1 = *(const ull*)&pbase[jj*PS + 2];
            lacc0 = fadd2(lacc0, pp0);
            lacc1 = fadd2(lacc1, pp1);
            #pragma unroll
            for (int k = 0; k < 8; k++) {
                ull wd = wbase[jj*64 + 8*k];
                acc[0][k] = ffma2(wd, pp0, acc[0][k]);
                acc[1][k] = ffma2(wd, pp1, acc[1][k]);
            }
        }
    }

    // ---- emit partials (additive across SPLIT) ----
    if (cgp == 0) {
        float l0, l1, l2, l3;
        unpack2(lacc0, l0, l1);
        unpack2(lacc1, l2, l3);
        size_t lb = (size_t)sp*ROWS_TOT + b*NN + i0 + rg*4;
        g_pl[lb]   = l0;
        g_pl[lb+1] = l1;
        g_pl[lb+2] = l2;
        g_pl[lb+3] = l3;
    }
    #pragma unroll
    for (int rp = 0; rp < 2; rp++) {
        size_t base0 = ((size_t)sp*ROWS_TOT + b*NN + i0 + rg*4 + 2*rp)     * HH2;
        size_t base1 = ((size_t)sp*ROWS_TOT + b*NN + i0 + rg*4 + 2*rp + 1) * HH2;
        #pragma unroll
        for (int k = 0; k < 8; k++) {
            float va, vb;
            unpack2(acc[rp][k], va, vb);
            g_pacc[base0 + cgp + 8*k] = va;
            g_pacc[base1 + cgp + 8*k] = vb;
        }
    }
}

// ============================================================================
// Kernel 5: combine additive split-K partials; normalize + elu.
// ============================================================================
__global__ void k_comb(float* __restrict__ out) {
    int tid = threadIdx.x;
    int r = blockIdx.x * 4 + (tid >> 6);
    int c = tid & 63;
    float l = 0.f, val = 0.f;
    #pragma unroll
    for (int s = 0; s < SPLIT; s++) {
        l   += g_pl[s*ROWS_TOT + r];
        val += g_pacc[((size_t)s*ROWS_TOT + r)*HH2 + c];
    }
    if (!(l > 0.f)) l = 1.f;
    float z = val / l;
    out[(size_t)r*HH2 + c] = z > 0.f ? z : expm1f(z);
}

// ============================================================================
extern "C" void kernel_launch(void* const* d_in, const int* in_sizes, int n_in,
                              void* d_out, int out_size) {
    const float* hist  = (const float*)d_in[0];
    const int*   adj   = (const int*)  d_in[1];
    const float* W1    = (const float*)d_in[2];
    const float* b1    = (const float*)d_in[3];
    const float* W_ih  = (const float*)d_in[4];
    const float* W_hh  = (const float*)d_in[5];
    const float* b_ih  = (const float*)d_in[6];
    const float* b_hh  = (const float*)d_in[7];
    const float* Wg    = (const float*)d_in[8];
    const float* a_src = (const float*)d_in[9];
    const float* a_dst = (const float*)d_in[10];
    float* out = (float*)d_out;

    const size_t sm_lstm = (size_t)(64*256 + 64*21) * sizeof(float);
    const size_t sm_gat  = (size_t)(64*64*8) + (size_t)(64*PS*4);
    cudaFuncSetAttribute(k_lstm2, cudaFuncAttributeMaxDynamicSharedMemorySize, (int)sm_lstm);
    cudaFuncSetAttribute(k_gat,   cudaFuncAttributeMaxDynamicSharedMemorySize, (int)sm_gat);

    dim3 g1(32, 8);
    k_h1   <<<g1, 256>>>(hist, W1, b1);
    k_wx   <<<2048, 256>>>(W_ih, b_ih, b_hh);
    k_lstm2<<<128,  256, sm_lstm>>>(W_hh);
    k_wh   <<<1024, 256>>>(Wg, a_src, a_dst);
    k_dmax <<<BB, 256>>>();
    dim3 g4(NN/TI, BB, SPLIT);
    k_gat  <<<g4, 256, sm_gat>>>(adj);
    k_comb <<<4096, 256>>>(out);
}

// round 9
// speedup vs baseline: 1.6219x; 1.0112x over previous
#include <cuda_runtime.h>
#include <math.h>
#include <stdint.h>

typedef unsigned long long ull;

#define BB   8
#define FHH  8
#define NN   2048
#define TINN 5
#define HH1  32
#define HH2  64
#define KXX  40
#define TI   256          // gat rows per CTA
#define PS   258          // PsT row stride (floats, even)
#define SPLIT 4
#define ROWS_TOT (BB*NN)

// ---------------- scratch ----------------------------------------------------
__device__ float g_h1[BB*NN*HH1];
__device__ float g_wx[BB*NN*4*HH2];
__device__ float g_hs[BB*NN*HH2];
__device__ float g_Wh[BB*NN*HH2];
__device__ float g_s [BB*NN];
__device__ float g_d [BB*NN];
__device__ float g_dmax[BB];
__device__ float g_pl  [SPLIT*ROWS_TOT];
__device__ float g_pacc[SPLIT*ROWS_TOT*HH2];

// ---------------- f32x2 helpers ----------------------------------------------
__device__ __forceinline__ ull pack2(float lo, float hi) {
    ull r; asm("mov.b64 %0, {%1, %2};" : "=l"(r) : "f"(lo), "f"(hi)); return r;
}
__device__ __forceinline__ void unpack2(ull v, float& lo, float& hi) {
    asm("mov.b64 {%0, %1}, %2;" : "=f"(lo), "=f"(hi) : "l"(v));
}
__device__ __forceinline__ ull ffma2(ull a, ull b, ull c) {
    ull r; asm("fma.rn.f32x2 %0, %1, %2, %3;" : "=l"(r) : "l"(a), "l"(b), "l"(c)); return r;
}
__device__ __forceinline__ ull fadd2(ull a, ull b) {
    ull r; asm("add.rn.f32x2 %0, %1, %2;" : "=l"(r) : "l"(a), "l"(b)); return r;
}
__device__ __forceinline__ float fsig(float x) { return __fdividef(1.f, 1.f + __expf(-x)); }
__device__ __forceinline__ float ftanh(float x) {
    return fmaf(__fdividef(2.f, 1.f + __expf(-2.f*x)), 1.f, -1.f);
}

// ============================================================================
// Kernel 1: h1 = elu(x @ W1^T + b1). Coalesced hist reads.
// ============================================================================
__global__ void k_h1(const float* __restrict__ hist,
                     const float* __restrict__ W1,
                     const float* __restrict__ b1) {
    __shared__ float xs[KXX*66];
    __shared__ float w1s[KXX*HH1];
    int tid = threadIdx.x;
    int n0 = blockIdx.x * 64;
    int t  = blockIdx.y;
    for (int i = tid; i < FHH*64*TINN; i += 256) {
        int f = i / 320, rem = i % 320;
        int n = rem / TINN, tt = rem % TINN;
        xs[(tt*FHH + f)*66 + n] = hist[((size_t)(t*FHH + f)*NN + n0)*TINN + rem];
    }
    for (int i = tid; i < HH1*KXX; i += 256) {
        int k = i / KXX, j = i % KXX;
        w1s[j*HH1 + k] = W1[i];
    }
    __syncthreads();
    int k  = tid & 31;
    int ng = tid >> 5;
    float bb = b1[k];
    #pragma unroll
    for (int q = 0; q < 8; q++) {
        int n = ng*8 + q;
        float acc = bb;
        #pragma unroll 8
        for (int j = 0; j < KXX; j++)
            acc = fmaf(xs[j*66 + n], w1s[j*HH1 + k], acc);
        acc = acc > 0.f ? acc : expm1f(acc);
        g_h1[(size_t)(t*NN + n0 + n)*HH1 + k] = acc;
    }
}

// ============================================================================
// Kernel 1b: wx = h1 @ W_ih^T + (b_ih+b_hh), interleaved [u*4+gt]
// ============================================================================
__global__ void k_wx(const float* __restrict__ W_ih,
                     const float* __restrict__ b_ih, const float* __restrict__ b_hh) {
    __shared__ float wih[HH1*256];
    __shared__ float bsI[256];
    __shared__ float h1s[HH1*9];
    int tid = threadIdx.x;
    int row0 = blockIdx.x * 8;
    for (int i = tid; i < HH1*256; i += 256) {
        int j = i >> 8, op = i & 255, u = op >> 2, gt = op & 3;
        wih[i] = W_ih[(gt*64 + u)*HH1 + j];
    }
    { int u = tid >> 2, gt = tid & 3; bsI[tid] = b_ih[gt*64+u] + b_hh[gt*64+u]; }
    { int r = tid & 7, j = tid >> 3; h1s[j*9 + r] = g_h1[(row0 + r)*HH1 + j]; }
    __syncthreads();

    int u  = tid & 63;
    int r0 = (tid >> 6) * 2;
    ull acc[2][2];
    ull b0 = *(const ull*)&bsI[u*4], b1v = *(const ull*)&bsI[u*4+2];
    acc[0][0]=b0; acc[0][1]=b1v; acc[1][0]=b0; acc[1][1]=b1v;
    #pragma unroll 8
    for (int j = 0; j < HH1; j++) {
        ulonglong2 wv = *(const ulonglong2*)&wih[j*256 + u*4];
        float ha = h1s[j*9 + r0], hb = h1s[j*9 + r0 + 1];
        ull ha2 = pack2(ha, ha), hb2 = pack2(hb, hb);
        acc[0][0] = ffma2(wv.x, ha2, acc[0][0]);
        acc[0][1] = ffma2(wv.y, ha2, acc[0][1]);
        acc[1][0] = ffma2(wv.x, hb2, acc[1][0]);
        acc[1][1] = ffma2(wv.y, hb2, acc[1][1]);
    }
    #pragma unroll
    for (int nd = 0; nd < 2; nd++) {
        float v0,v1,v2,v3;
        unpack2(acc[nd][0], v0, v1);
        unpack2(acc[nd][1], v2, v3);
        *(float4*)&g_wx[(size_t)(row0 + r0 + nd)*256 + u*4] = make_float4(v0,v1,v2,v3);
    }
}

// ============================================================================
// Kernel 2: recurrent LSTM (W_hh part). 256 blocks x 256 thr, 8 nodes/block.
// thread = (unit u) x (2 nodes). Gates interleaved [u*4+gt].
// ============================================================================
__global__ void __launch_bounds__(256) k_lstm2(const float* __restrict__ W_hh) {
    extern __shared__ float sm[];
    float* whh = sm;                  // [64][256], 64KB
    float* hsh = whh + 64*256;        // [j=unit][node] pad 9

    int tid = threadIdx.x;
    for (int i = tid; i < 64*256; i += 256) {
        int j = i >> 8, op = i & 255, u = op >> 2, gt = op & 3;
        whh[i] = W_hh[(gt*64 + u)*HH2 + j];
    }
    for (int i = tid; i < 64*9; i += 256) hsh[i] = 0.f;

    int u  = tid & 63;
    int nq = tid >> 6;                // 0..3 -> nodes nq*2, nq*2+1
    int node0 = blockIdx.x * 8 + nq*2;

    float c[2] = {0.f,0.f};
    float4 wx4[2];
    #pragma unroll
    for (int n = 0; n < 2; n++)
        wx4[n] = *(const float4*)&g_wx[(size_t)(node0 + n)*256 + u*4];

    for (int t = 0; t < BB; t++) {
        __syncthreads();
        ull acc[2][2];
        #pragma unroll
        for (int n = 0; n < 2; n++) {
            acc[n][0] = pack2(wx4[n].x, wx4[n].y);
            acc[n][1] = pack2(wx4[n].z, wx4[n].w);
        }
        if (t < BB-1) {
            #pragma unroll
            for (int n = 0; n < 2; n++)
                wx4[n] = *(const float4*)&g_wx[(size_t)((t+1)*NN + node0 + n)*256 + u*4];
        }
        #pragma unroll 8
        for (int j = 0; j < HH2; j++) {
            ulonglong2 wv = *(const ulonglong2*)&whh[j*256 + u*4];
            #pragma unroll
            for (int n = 0; n < 2; n++) {
                float hv = hsh[j*9 + nq*2 + n];
                ull hv2 = pack2(hv, hv);
                acc[n][0] = ffma2(wv.x, hv2, acc[n][0]);
                acc[n][1] = ffma2(wv.y, hv2, acc[n][1]);
            }
        }
        __syncthreads();
        #pragma unroll
        for (int n = 0; n < 2; n++) {
            float gi,gf,gg,go;
            unpack2(acc[n][0], gi, gf);
            unpack2(acc[n][1], gg, go);
            c[n] = fsig(gf)*c[n] + fsig(gi)*ftanh(gg);
            float h = fsig(go)*ftanh(c[n]);
            hsh[u*9 + nq*2 + n] = h;
            g_hs[(size_t)(t*NN + node0 + n)*HH2 + u] = h;
        }
    }
}

// ============================================================================
// Kernel 3: Wh = hs @ Wg ; s = Wh.a_src ; d = Wh.a_dst. 64 rows/block.
// ============================================================================
__global__ void k_wh(const float* __restrict__ Wg,
                     const float* __restrict__ a_src,
                     const float* __restrict__ a_dst) {
    __shared__ float wgs[64*64];      // 16KB
    __shared__ float hss[64*65];      // [u][m] 16.6KB
    int tid = threadIdx.x;
    int row0 = blockIdx.x * 64;
    for (int i = tid; i < 4096; i += 256) wgs[i] = Wg[i];
    for (int i = tid; i < 4096; i += 256) {
        int mm = i >> 6, u = i & 63;
        hss[u*65 + mm] = g_hs[(size_t)(row0 + mm)*HH2 + u];
    }
    __syncthreads();
    int cq = tid & 15;
    int c0 = cq * 4;
    float as0 = a_src[c0], as1 = a_src[c0+1], as2 = a_src[c0+2], as3 = a_src[c0+3];
    float ad0 = a_dst[c0], ad1 = a_dst[c0+1], ad2 = a_dst[c0+2], ad3 = a_dst[c0+3];
    #pragma unroll
    for (int rr = 0; rr < 4; rr++) {
        int m = rr*16 + (tid >> 4);
        ull acc0 = 0ull, acc1 = 0ull;
        #pragma unroll 8
        for (int u = 0; u < 64; u++) {
            float hv = hss[u*65 + m];
            ull hv2 = pack2(hv, hv);
            acc0 = ffma2(*(const ull*)&wgs[u*64 + c0],     hv2, acc0);
            acc1 = ffma2(*(const ull*)&wgs[u*64 + c0 + 2], hv2, acc1);
        }
        float wh0, wh1, wh2, wh3;
        unpack2(acc0, wh0, wh1);
        unpack2(acc1, wh2, wh3);
        *(float4*)&g_Wh[(size_t)(row0 + m)*HH2 + c0] = make_float4(wh0, wh1, wh2, wh3);
        float psum = wh0*as0 + wh1*as1 + wh2*as2 + wh3*as3;
        float dsum = wh0*ad0 + wh1*ad1 + wh2*ad2 + wh3*ad3;
        #pragma unroll
        for (int o = 8; o > 0; o >>= 1) {
            psum += __shfl_xor_sync(0xffffffffu, psum, o);
            dsum += __shfl_xor_sync(0xffffffffu, dsum, o);
        }
        if (cq == 0) {
            g_s[row0 + m] = psum;
            g_d[row0 + m] = dsum;
        }
    }
}

// ============================================================================
// Kernel 3c: per-batch max of d
// ============================================================================
__global__ void k_dmax() {
    __shared__ float red[8];
    int b = blockIdx.x, tid = threadIdx.x;
    float m = -1e30f;
    for (int i = tid; i < NN; i += 256) m = fmaxf(m, g_d[b*NN + i]);
    #pragma unroll
    for (int o = 16; o > 0; o >>= 1)
        m = fmaxf(m, __shfl_xor_sync(0xffffffffu, m, o));
    if ((tid & 31) == 0) red[tid >> 5] = m;
    __syncthreads();
    if (tid == 0) {
        float mm = red[0];
        #pragma unroll
        for (int q = 1; q < 8; q++) mm = fmaxf(mm, red[q]);
        g_dmax[b] = mm;
    }
}

// ============================================================================
// Kernel 4: GAT. Exp-free P (rank-1 factorization, fixed shift), l folded
// into GEMM (fadd2), adj front-batched. grid (8, 8, SPLIT), 256 thr, 2 CTA/SM.
// Thread tile 8 rows x 8 cols: per jj = 12 LDS.64 + 4 fadd2 + 32 ffma2.
// ============================================================================
__global__ void __launch_bounds__(256, 2) k_gat(const int* __restrict__ adj) {
    extern __shared__ char smraw[];
    ull*   whs = (ull*)smraw;                      // [jj][c] dup pairs, 32KB
    float* PsT = (float*)(smraw + 32768);          // [jj][ii] stride PS, 66KB
    __shared__ float4 row_sh[TI];                  // (thr, Ap, An, -)

    int tid = threadIdx.x, lane = tid & 31, w = tid >> 5;
    int b = blockIdx.y, i0 = blockIdx.x * TI, sp = blockIdx.z;

    float dmax = g_dmax[b];
    {
        float s = g_s[b*NN + i0 + tid];
        float sm = s + dmax;
        float M = sm > 0.f ? sm : 0.2f*sm;
        row_sh[tid] = make_float4(-s, __expf(sm - M), __expf(0.2f*sm - M), 0.f);
    }

    int rg  = tid >> 3;      // 32 row groups x 8 rows
    int cgp = tid & 7;       // cols cgp + 8k
    ull acc[4][8];
    #pragma unroll
    for (int rp = 0; rp < 4; rp++)
        #pragma unroll
        for (int k = 0; k < 8; k++) acc[rp][k] = 0ull;
    ull lacc[4] = {0ull, 0ull, 0ull, 0ull};

    const int* adjb = adj + (size_t)(b*2 + 1) * NN * NN;
    const int JT = (NN/64)/SPLIT;

    for (int jtl = 0; jtl < JT; jtl++) {
        int j0 = (sp * JT + jtl) * 64;
        __syncthreads();                 // prev GEMM done reading smem

        for (int i = tid; i < 2048; i += 256) {
            float2 v = *(const float2*)&g_Wh[(size_t)(b*NN + j0)*64 + 2*i];
            whs[2*i]   = pack2(v.x, v.x);
            whs[2*i+1] = pack2(v.y, v.y);
        }

        float d0 = g_d[b*NN + j0 + lane];
        float d1 = g_d[b*NN + j0 + lane + 32];
        float bp0 = __expf(d0 - dmax);
        float bp1 = __expf(d1 - dmax);
        float bm0 = __expf(0.2f*(d0 - dmax));
        float bm1 = __expf(0.2f*(d1 - dmax));

        // P-phase: warp w -> rows w*32..w*32+31, 4 batches of 8
        #pragma unroll
        for (int batch = 0; batch < 4; batch++) {
            const int* ab = adjb + (size_t)(i0 + w*32 + batch*8)*NN + j0;
            int a0[8], a1[8];
            #pragma unroll
            for (int q = 0; q < 8; q++) {
                a0[q] = ab[(size_t)q*NN + lane];
                a1[q] = ab[(size_t)q*NN + lane + 32];
            }
            #pragma unroll
            for (int q = 0; q < 8; q++) {
                int ii = w*32 + batch*8 + q;
                float4 rs = row_sh[ii];
                float c0 = (d0 > rs.x) ? rs.y*bp0 : rs.z*bm0;
                float c1 = (d1 > rs.x) ? rs.y*bp1 : rs.z*bm1;
                c0 = a0[q] > 0 ? c0 : 0.f;
                c1 = a1[q] > 0 ? c1 : 0.f;
                PsT[lane*PS + ii]      = c0;
                PsT[(lane+32)*PS + ii] = c1;
            }
        }
        __syncthreads();

        // GEMM: rows rg*8 + {0..7} (4 ull pairs), cols cgp + 8k
        const float* pbase = PsT + rg*8;
        const ull*   wbase = whs + cgp;
        #pragma unroll 2
        for (int jj = 0; jj < 64; jj++) {
            ull pp[4];
            #pragma unroll
            for (int rp = 0; rp < 4; rp++)
                pp[rp] = *(const ull*)&pbase[jj*PS + 2*rp];
            #pragma unroll
            for (int rp = 0; rp < 4; rp++)
                lacc[rp] = fadd2(lacc[rp], pp[rp]);
            #pragma unroll
            for (int k = 0; k < 8; k++) {
                ull wd = wbase[jj*64 + 8*k];
                #pragma unroll
                for (int rp = 0; rp < 4; rp++)
                    acc[rp][k] = ffma2(wd, pp[rp], acc[rp][k]);
            }
        }
    }

    // ---- emit partials (additive across SPLIT) ----
    if (cgp == 0) {
        size_t lb = (size_t)sp*ROWS_TOT + b*NN + i0 + rg*8;
        #pragma unroll
        for (int rp = 0; rp < 4; rp++) {
            float l0, l1;
            unpack2(lacc[rp], l0, l1);
            g_pl[lb + 2*rp]     = l0;
            g_pl[lb + 2*rp + 1] = l1;
        }
    }
    #pragma unroll
    for (int rp = 0; rp < 4; rp++) {
        size_t base0 = ((size_t)sp*ROWS_TOT + b*NN + i0 + rg*8 + 2*rp)     * HH2;
        size_t base1 = ((size_t)sp*ROWS_TOT + b*NN + i0 + rg*8 + 2*rp + 1) * HH2;
        #pragma unroll
        for (int k = 0; k < 8; k++) {
            float va, vb;
            unpack2(acc[rp][k], va, vb);
            g_pacc[base0 + cgp + 8*k] = va;
            g_pacc[base1 + cgp + 8*k] = vb;
        }
    }
}

// ============================================================================
// Kernel 5: combine additive split-K partials; normalize + elu.
// ============================================================================
__global__ void k_comb(float* __restrict__ out) {
    int tid = threadIdx.x;
    int r = blockIdx.x * 4 + (tid >> 6);
    int c = tid & 63;
    float l = 0.f, val = 0.f;
    #pragma unroll
    for (int s = 0; s < SPLIT; s++) {
        l   += g_pl[s*ROWS_TOT + r];
        val += g_pacc[((size_t)s*ROWS_TOT + r)*HH2 + c];
    }
    if (!(l > 0.f)) l = 1.f;
    float z = val / l;
    out[(size_t)r*HH2 + c] = z > 0.f ? z : expm1f(z);
}

// ============================================================================
extern "C" void kernel_launch(void* const* d_in, const int* in_sizes, int n_in,
                              void* d_out, int out_size) {
    const float* hist  = (const float*)d_in[0];
    const int*   adj   = (const int*)  d_in[1];
    const float* W1    = (const float*)d_in[2];
    const float* b1    = (const float*)d_in[3];
    const float* W_ih  = (const float*)d_in[4];
    const float* W_hh  = (const float*)d_in[5];
    const float* b_ih  = (const float*)d_in[6];
    const float* b_hh  = (const float*)d_in[7];
    const float* Wg    = (const float*)d_in[8];
    const float* a_src = (const float*)d_in[9];
    const float* a_dst = (const float*)d_in[10];
    float* out = (float*)d_out;

    const size_t sm_lstm = (size_t)(64*256 + 64*9) * sizeof(float);
    const size_t sm_gat  = (size_t)32768 + (size_t)(64*PS*4);
    cudaFuncSetAttribute(k_lstm2, cudaFuncAttributeMaxDynamicSharedMemorySize, (int)sm_lstm);
    cudaFuncSetAttribute(k_gat,   cudaFuncAttributeMaxDynamicSharedMemorySize, (int)sm_gat);

    dim3 g1(32, 8);
    k_h1   <<<g1, 256>>>(hist, W1, b1);
    k_wx   <<<2048, 256>>>(W_ih, b_ih, b_hh);
    k_lstm2<<<256,  256, sm_lstm>>>(W_hh);
    k_wh   <<<256, 256>>>(Wg, a_src, a_dst);
    k_dmax <<<BB, 256>>>();
    dim3 g4(NN/TI, BB, SPLIT);
    k_gat  <<<g4, 256, sm_gat>>>(adj);
    k_comb <<<4096, 256>>>(out);
}

// round 11
// speedup vs baseline: 1.6576x; 1.0220x over previous
#include <cuda_runtime.h>
#include <math.h>
#include <stdint.h>

typedef unsigned long long ull;

#define BB   8
#define FHH  8
#define NN   2048
#define TINN 5
#define HH1  32
#define HH2  64
#define KXX  40
#define TI   256          // gat rows per CTA
#define PS   258          // PsT row stride (floats, even)
#define SPLIT 4
#define ROWS_TOT (BB*NN)

// ---------------- scratch ----------------------------------------------------
__device__ float g_wx[BB*NN*4*HH2];
__device__ float g_hs[BB*NN*HH2];
__device__ float g_Wh[BB*NN*HH2];
__device__ float g_s [BB*NN];
__device__ float g_d [BB*NN];
__device__ unsigned int g_dmaxb[BB];
__device__ float g_pl  [SPLIT*ROWS_TOT];
__device__ float g_pacc[SPLIT*ROWS_TOT*HH2];

// ---------------- f32x2 helpers ----------------------------------------------
__device__ __forceinline__ ull pack2(float lo, float hi) {
    ull r; asm("mov.b64 %0, {%1, %2};" : "=l"(r) : "f"(lo), "f"(hi)); return r;
}
__device__ __forceinline__ void unpack2(ull v, float& lo, float& hi) {
    asm("mov.b64 {%0, %1}, %2;" : "=f"(lo), "=f"(hi) : "l"(v));
}
__device__ __forceinline__ ull ffma2(ull a, ull b, ull c) {
    ull r; asm("fma.rn.f32x2 %0, %1, %2, %3;" : "=l"(r) : "l"(a), "l"(b), "l"(c)); return r;
}
__device__ __forceinline__ ull fadd2(ull a, ull b) {
    ull r; asm("add.rn.f32x2 %0, %1, %2;" : "=l"(r) : "l"(a), "l"(b)); return r;
}
__device__ __forceinline__ float fsig(float x) { return __fdividef(1.f, 1.f + __expf(-x)); }
__device__ __forceinline__ float ftanh(float x) {
    return fmaf(__fdividef(2.f, 1.f + __expf(-2.f*x)), 1.f, -1.f);
}
// order-preserving float<->uint for atomicMax
__device__ __forceinline__ unsigned int fkey(float f) {
    unsigned int b = __float_as_uint(f);
    return (b & 0x80000000u) ? ~b : (b | 0x80000000u);
}
__device__ __forceinline__ float fdec(unsigned int k) {
    return __uint_as_float((k & 0x80000000u) ? (k ^ 0x80000000u) : ~k);
}

// ============================================================================
// Kernel 1: fused h1 = elu(x@W1^T+b1) and wx = h1@W_ih^T + (b_ih+b_hh).
// grid 2048 x 256 thr, 8 rows/block. Also zero-inits g_dmaxb.
// ============================================================================
__global__ void k_hw(const float* __restrict__ hist,
                     const float* __restrict__ W1,
                     const float* __restrict__ b1,
                     const float* __restrict__ W_ih,
                     const float* __restrict__ b_ih,
                     const float* __restrict__ b_hh) {
    __shared__ float xs[KXX*9];       // [k][r]
    __shared__ float w1s[KXX*HH1];    // [k][j]
    __shared__ float wih[HH1*256];    // [j][u*4+gt]
    __shared__ float bsI[256];
    __shared__ float h1s[HH1*9];      // [j][r]
    int tid = threadIdx.x;
    int row0 = blockIdx.x * 8;
    int t  = row0 >> 11;              // row0 / NN
    int n0 = row0 & (NN-1);

    if (blockIdx.x == 0 && tid < BB) g_dmaxb[tid] = 0u;

    for (int i = tid; i < FHH*8*TINN; i += 256) {   // 320 elements, strided!
        int f = i / 40, rem = i % 40;
        int n = rem / TINN, tt = rem % TINN;
        xs[(tt*FHH + f)*9 + n] = hist[((size_t)(t*FHH + f)*NN + n0 + n)*TINN + tt];
    }
    for (int i = tid; i < KXX*HH1; i += 256) {
        int k = i / KXX, idx = i % KXX;
        w1s[idx*HH1 + k] = W1[i];
    }
    for (int i = tid; i < HH1*256; i += 256) {
        int j = i >> 8, op = i & 255, u = op >> 2, gt = op & 3;
        wih[i] = W_ih[(gt*64 + u)*HH1 + j];
    }
    { int u = tid >> 2, gt = tid & 3; bsI[tid] = b_ih[gt*64+u] + b_hh[gt*64+u]; }
    __syncthreads();

    // h1: thread -> (r = tid>>5, j = tid&31)
    {
        int r = tid >> 5, j = tid & 31;
        float acc = b1[j];
        #pragma unroll 8
        for (int k = 0; k < KXX; k++)
            acc = fmaf(xs[k*9 + r], w1s[k*HH1 + j], acc);
        acc = acc > 0.f ? acc : expm1f(acc);
        h1s[j*9 + r] = acc;
    }
    __syncthreads();

    // wx: thread -> (u = tid&63, rows r0, r0+1)
    int u  = tid & 63;
    int r0 = (tid >> 6) * 2;
    ull acc[2][2];
    ull b0 = *(const ull*)&bsI[u*4], b1v = *(const ull*)&bsI[u*4+2];
    acc[0][0]=b0; acc[0][1]=b1v; acc[1][0]=b0; acc[1][1]=b1v;
    #pragma unroll 8
    for (int j = 0; j < HH1; j++) {
        ulonglong2 wv = *(const ulonglong2*)&wih[j*256 + u*4];
        float ha = h1s[j*9 + r0], hb = h1s[j*9 + r0 + 1];
        ull ha2 = pack2(ha, ha), hb2 = pack2(hb, hb);
        acc[0][0] = ffma2(wv.x, ha2, acc[0][0]);
        acc[0][1] = ffma2(wv.y, ha2, acc[0][1]);
        acc[1][0] = ffma2(wv.x, hb2, acc[1][0]);
        acc[1][1] = ffma2(wv.y, hb2, acc[1][1]);
    }
    #pragma unroll
    for (int nd = 0; nd < 2; nd++) {
        float v0,v1,v2,v3;
        unpack2(acc[nd][0], v0, v1);
        unpack2(acc[nd][1], v2, v3);
        *(float4*)&g_wx[(size_t)(row0 + r0 + nd)*256 + u*4] = make_float4(v0,v1,v2,v3);
    }
}

// ============================================================================
// Kernel 2: recurrent LSTM (W_hh part). 256 blocks x 256 thr, 8 nodes/block.
// ============================================================================
__global__ void __launch_bounds__(256) k_lstm2(const float* __restrict__ W_hh) {
    extern __shared__ float sm[];
    float* whh = sm;                  // [64][256], 64KB
    float* hsh = whh + 64*256;        // [j=unit][node] pad 9

    int tid = threadIdx.x;
    for (int i = tid; i < 64*256; i += 256) {
        int j = i >> 8, op = i & 255, u = op >> 2, gt = op & 3;
        whh[i] = W_hh[(gt*64 + u)*HH2 + j];
    }
    for (int i = tid; i < 64*9; i += 256) hsh[i] = 0.f;

    int u  = tid & 63;
    int nq = tid >> 6;
    int node0 = blockIdx.x * 8 + nq*2;

    float c[2] = {0.f,0.f};
    float4 wx4[2];
    #pragma unroll
    for (int n = 0; n < 2; n++)
        wx4[n] = *(const float4*)&g_wx[(size_t)(node0 + n)*256 + u*4];

    for (int t = 0; t < BB; t++) {
        __syncthreads();
        ull acc[2][2];
        #pragma unroll
        for (int n = 0; n < 2; n++) {
            acc[n][0] = pack2(wx4[n].x, wx4[n].y);
            acc[n][1] = pack2(wx4[n].z, wx4[n].w);
        }
        if (t < BB-1) {
            #pragma unroll
            for (int n = 0; n < 2; n++)
                wx4[n] = *(const float4*)&g_wx[(size_t)((t+1)*NN + node0 + n)*256 + u*4];
        }
        #pragma unroll 8
        for (int j = 0; j < HH2; j++) {
            ulonglong2 wv = *(const ulonglong2*)&whh[j*256 + u*4];
            #pragma unroll
            for (int n = 0; n < 2; n++) {
                float hv = hsh[j*9 + nq*2 + n];
                ull hv2 = pack2(hv, hv);
                acc[n][0] = ffma2(wv.x, hv2, acc[n][0]);
                acc[n][1] = ffma2(wv.y, hv2, acc[n][1]);
            }
        }
        __syncthreads();
        #pragma unroll
        for (int n = 0; n < 2; n++) {
            float gi,gf,gg,go;
            unpack2(acc[n][0], gi, gf);
            unpack2(acc[n][1], gg, go);
            c[n] = fsig(gf)*c[n] + fsig(gi)*ftanh(gg);
            float h = fsig(go)*ftanh(c[n]);
            hsh[u*9 + nq*2 + n] = h;
            g_hs[(size_t)(t*NN + node0 + n)*HH2 + u] = h;
        }
    }
}

// ============================================================================
// Kernel 3: Wh = hs @ Wg ; s,d; per-block dmax atomic. 512 blocks x 32 rows.
// ============================================================================
__global__ void k_wh(const float* __restrict__ Wg,
                     const float* __restrict__ a_src,
                     const float* __restrict__ a_dst) {
    __shared__ float wgs[64*64];      // 16KB
    __shared__ float hss[64*33];      // [u][m]
    __shared__ float dred[32];
    int tid = threadIdx.x;
    int row0 = blockIdx.x * 32;
    for (int i = tid; i < 4096; i += 256) wgs[i] = Wg[i];
    for (int i = tid; i < 2048; i += 256) {
        int mm = i >> 6, u = i & 63;
        hss[u*33 + mm] = g_hs[(size_t)(row0 + mm)*HH2 + u];
    }
    __syncthreads();
    int cq = tid & 15;
    int c0 = cq * 4;
    float as0 = a_src[c0], as1 = a_src[c0+1], as2 = a_src[c0+2], as3 = a_src[c0+3];
    float ad0 = a_dst[c0], ad1 = a_dst[c0+1], ad2 = a_dst[c0+2], ad3 = a_dst[c0+3];
    #pragma unroll
    for (int rr = 0; rr < 2; rr++) {
        int m = rr*16 + (tid >> 4);
        ull acc0 = 0ull, acc1 = 0ull;
        #pragma unroll 8
        for (int u = 0; u < 64; u++) {
            float hv = hss[u*33 + m];
            ull hv2 = pack2(hv, hv);
            acc0 = ffma2(*(const ull*)&wgs[u*64 + c0],     hv2, acc0);
            acc1 = ffma2(*(const ull*)&wgs[u*64 + c0 + 2], hv2, acc1);
        }
        float wh0, wh1, wh2, wh3;
        unpack2(acc0, wh0, wh1);
        unpack2(acc1, wh2, wh3);
        *(float4*)&g_Wh[(size_t)(row0 + m)*HH2 + c0] = make_float4(wh0, wh1, wh2, wh3);
        float psum = wh0*as0 + wh1*as1 + wh2*as2 + wh3*as3;
        float dsum = wh0*ad0 + wh1*ad1 + wh2*ad2 + wh3*ad3;
        #pragma unroll
        for (int o = 8; o > 0; o >>= 1) {
            psum += __shfl_xor_sync(0xffffffffu, psum, o);
            dsum += __shfl_xor_sync(0xffffffffu, dsum, o);
        }
        if (cq == 0) {
            g_s[row0 + m] = psum;
            g_d[row0 + m] = dsum;
            dred[m] = dsum;
        }
    }
    __syncthreads();
    if (tid == 0) {
        float mx = dred[0];
        #pragma unroll
        for (int q = 1; q < 32; q++) mx = fmaxf(mx, dred[q]);
        atomicMax(&g_dmaxb[row0 >> 11], fkey(mx));
    }
}

// ============================================================================
// Kernel 4: GAT. Exp-free P (rank-1 factorization, fixed shift), l folded
// into GEMM (fadd2), adj front-batched. grid (8, 8, SPLIT), 256 thr, 2 CTA/SM.
// ============================================================================
__global__ void __launch_bounds__(256, 2) k_gat(const int* __restrict__ adj) {
    extern __shared__ char smraw[];
    ull*   whs = (ull*)smraw;                      // [jj][c] dup pairs, 32KB
    float* PsT = (float*)(smraw + 32768);          // [jj][ii] stride PS, 66KB
    __shared__ float4 row_sh[TI];                  // (thr, Ap, An, -)

    int tid = threadIdx.x, lane = tid & 31, w = tid >> 5;
    int b = blockIdx.y, i0 = blockIdx.x * TI, sp = blockIdx.z;

    float dmax = fdec(g_dmaxb[b]);
    {
        float s = g_s[b*NN + i0 + tid];
        float sm = s + dmax;
        float M = sm > 0.f ? sm : 0.2f*sm;
        row_sh[tid] = make_float4(-s, __expf(sm - M), __expf(0.2f*sm - M), 0.f);
    }

    int rg  = tid >> 3;      // 32 row groups x 8 rows
    int cgp = tid & 7;       // cols cgp + 8k
    ull acc[4][8];
    #pragma unroll
    for (int rp = 0; rp < 4; rp++)
        #pragma unroll
        for (int k = 0; k < 8; k++) acc[rp][k] = 0ull;
    ull lacc[4] = {0ull, 0ull, 0ull, 0ull};

    const int* adjb = adj + (size_t)(b*2 + 1) * NN * NN;
    const int JT = (NN/64)/SPLIT;

    for (int jtl = 0; jtl < JT; jtl++) {
        int j0 = (sp * JT + jtl) * 64;
        __syncthreads();

        for (int i = tid; i < 2048; i += 256) {
            float2 v = *(const float2*)&g_Wh[(size_t)(b*NN + j0)*64 + 2*i];
            whs[2*i]   = pack2(v.x, v.x);
            whs[2*i+1] = pack2(v.y, v.y);
        }

        float d0 = g_d[b*NN + j0 + lane];
        float d1 = g_d[b*NN + j0 + lane + 32];
        float bp0 = __expf(d0 - dmax);
        float bp1 = __expf(d1 - dmax);
        float bm0 = __expf(0.2f*(d0 - dmax));
        float bm1 = __expf(0.2f*(d1 - dmax));

        #pragma unroll
        for (int batch = 0; batch < 4; batch++) {
            const int* ab = adjb + (size_t)(i0 + w*32 + batch*8)*NN + j0;
            int a0[8], a1[8];
            #pragma unroll
            for (int q = 0; q < 8; q++) {
                a0[q] = ab[(size_t)q*NN + lane];
                a1[q] = ab[(size_t)q*NN + lane + 32];
            }
            #pragma unroll
            for (int q = 0; q < 8; q++) {
                int ii = w*32 + batch*8 + q;
                float4 rs = row_sh[ii];
                float c0 = (d0 > rs.x) ? rs.y*bp0 : rs.z*bm0;
                float c1 = (d1 > rs.x) ? rs.y*bp1 : rs.z*bm1;
                c0 = a0[q] > 0 ? c0 : 0.f;
                c1 = a1[q] > 0 ? c1 : 0.f;
                PsT[lane*PS + ii]      = c0;
                PsT[(lane+32)*PS + ii] = c1;
            }
        }
        __syncthreads();

        const float* pbase = PsT + rg*8;
        const ull*   wbase = whs + cgp;
        #pragma unroll 2
        for (int jj = 0; jj < 64; jj++) {
            ull pp[4];
            #pragma unroll
            for (int rp = 0; rp < 4; rp++)
                pp[rp] = *(const ull*)&pbase[jj*PS + 2*rp];
            #pragma unroll
            for (int rp = 0; rp < 4; rp++)
                lacc[rp] = fadd2(lacc[rp], pp[rp]);
            #pragma unroll
            for (int k = 0; k < 8; k++) {
                ull wd = wbase[jj*64 + 8*k];
                #pragma unroll
                for (int rp = 0; rp < 4; rp++)
                    acc[rp][k] = ffma2(wd, pp[rp], acc[rp][k]);
            }
        }
    }

    if (cgp == 0) {
        size_t lb = (size_t)sp*ROWS_TOT + b*NN + i0 + rg*8;
        #pragma unroll
        for (int rp = 0; rp < 4; rp++) {
            float l0, l1;
            unpack2(lacc[rp], l0, l1);
            g_pl[lb + 2*rp]     = l0;
            g_pl[lb + 2*rp + 1] = l1;
        }
    }
    #pragma unroll
    for (int rp = 0; rp < 4; rp++) {
        size_t base0 = ((size_t)sp*ROWS_TOT + b*NN + i0 + rg*8 + 2*rp)     * HH2;
        size_t base1 = ((size_t)sp*ROWS_TOT + b*NN + i0 + rg*8 + 2*rp + 1) * HH2;
        #pragma unroll
        for (int k = 0; k < 8; k++) {
            float va, vb;
            unpack2(acc[rp][k], va, vb);
            g_pacc[base0 + cgp + 8*k] = va;
            g_pacc[base1 + cgp + 8*k] = vb;
        }
    }
}

// ============================================================================
// Kernel 5: combine additive split-K partials; normalize + elu.
// ============================================================================
__global__ void k_comb(float* __restrict__ out) {
    int tid = threadIdx.x;
    int r = blockIdx.x * 4 + (tid >> 6);
    int c = tid & 63;
    float l = 0.f, val = 0.f;
    #pragma unroll
    for (int s = 0; s < SPLIT; s++) {
        l   += g_pl[s*ROWS_TOT + r];
        val += g_pacc[((size_t)s*ROWS_TOT + r)*HH2 + c];
    }
    if (!(l > 0.f)) l = 1.f;
    float z = val / l;
    out[(size_t)r*HH2 + c] = z > 0.f ? z : expm1f(z);
}

// ============================================================================
extern "C" void kernel_launch(void* const* d_in, const int* in_sizes, int n_in,
                              void* d_out, int out_size) {
    const float* hist  = (const float*)d_in[0];
    const int*   adj   = (const int*)  d_in[1];
    const float* W1    = (const float*)d_in[2];
    const float* b1    = (const float*)d_in[3];
    const float* W_ih  = (const float*)d_in[4];
    const float* W_hh  = (const float*)d_in[5];
    const float* b_ih  = (const float*)d_in[6];
    const float* b_hh  = (const float*)d_in[7];
    const float* Wg    = (const float*)d_in[8];
    const float* a_src = (const float*)d_in[9];
    const float* a_dst = (const float*)d_in[10];
    float* out = (float*)d_out;

    const size_t sm_lstm = (size_t)(64*256 + 64*9) * sizeof(float);
    const size_t sm_gat  = (size_t)32768 + (size_t)(64*PS*4);
    cudaFuncSetAttribute(k_lstm2, cudaFuncAttributeMaxDynamicSharedMemorySize, (int)sm_lstm);
    cudaFuncSetAttribute(k_gat,   cudaFuncAttributeMaxDynamicSharedMemorySize, (int)sm_gat);

    k_hw   <<<2048, 256>>>(hist, W1, b1, W_ih, b_ih, b_hh);
    k_lstm2<<<256,  256, sm_lstm>>>(W_hh);
    k_wh   <<<512,  256>>>(Wg, a_src, a_dst);
    dim3 g4(NN/TI, BB, SPLIT);
    k_gat  <<<g4, 256, sm_gat>>>(adj);
    k_comb <<<4096, 256>>>(out);
}